// round 14
// baseline (speedup 1.0000x reference)
#include <cuda_runtime.h>
#include <cuda_fp16.h>
#include <math.h>
#include <stdint.h>

typedef __half h16;

// ---------------------------------------------------------------------------
// HiLoAttention: B=8, N=4096 (64x64), C=512, heads=8, hd=64, window=2
// Round 14: GEMM back to 64x64 warp tiles (4 warps, 128 thr) — halves
// LDSM bytes/MMA (192->128B), balancing smem port vs tensor pipe.
// Everything else unchanged from R13 (single-product fp16 GEMMs, fp16 qcat,
// compensated hi-attn, fused lo+upsample).
// ---------------------------------------------------------------------------

__device__ h16   g_Ahi[40960ull * 512];
__device__ h16   g_Wqh[1536 * 512];
__device__ h16   g_Wph[512 * 512];
__device__ h16   g_qcat[40960ull * 1536];     // only lo rows (>=8192) used
__device__ float g_ahi[8 * 1024 * 512];
__device__ h16   g_Phi[32768ull * 512];
__device__ h16   g_Qh[8 * 8 * 1024 * 64];
__device__ h16   g_Ql[8 * 8 * 1024 * 64];
__device__ h16   g_Kh[8 * 8 * 1024 * 64];
__device__ h16   g_Vh[8 * 8 * 1024 * 64];

// ------------------------------ helpers -------------------------------------
__device__ __forceinline__ uint32_t smem_u32(const void* p) {
    uint32_t a;
    asm("{ .reg .u64 t; cvta.to.shared.u64 t, %1; cvt.u32.u64 %0, t; }"
        : "=r"(a) : "l"(p));
    return a;
}
__device__ __forceinline__ void cp16(uint32_t dst, const void* src) {
    asm volatile("cp.async.cg.shared.global [%0], [%1], 16;"
                 :: "r"(dst), "l"(src) : "memory");
}
__device__ __forceinline__ uint32_t sw128(uint32_t off) {
    return off ^ ((off >> 3) & 0x70);
}
__device__ __forceinline__ void pack_split_h(float p0, float p1,
                                             uint32_t* hi, uint32_t* lo) {
    __half2 h2 = __floats2half2_rn(p0, p1);
    float2 f = __half22float2(h2);
    __half2 l2 = __floats2half2_rn(p0 - f.x, p1 - f.y);
    *hi = *(uint32_t*)&h2;
    *lo = *(uint32_t*)&l2;
}
__device__ __forceinline__ uint32_t pack_round_h(float p0, float p1) {
    __half2 h2 = __floats2half2_rn(p0, p1);
    return *(uint32_t*)&h2;
}
__device__ __forceinline__ void round4_store(float4 v, h16* H, size_t off) {
    uint2 o = make_uint2(pack_round_h(v.x, v.y), pack_round_h(v.z, v.w));
    *(uint2*)(H + off) = o;
}

#define LDSM4(r, addr)                                                        \
    asm volatile("ldmatrix.sync.aligned.m8n8.x4.shared.b16 {%0,%1,%2,%3}, [%4];" \
                 : "=r"((r)[0]), "=r"((r)[1]), "=r"((r)[2]), "=r"((r)[3])     \
                 : "r"(addr))

#define LDSM4T(r, addr)                                                       \
    asm volatile("ldmatrix.sync.aligned.m8n8.x4.trans.shared.b16 {%0,%1,%2,%3}, [%4];" \
                 : "=r"((r)[0]), "=r"((r)[1]), "=r"((r)[2]), "=r"((r)[3])     \
                 : "r"(addr))

#define MMA16816(c, a, b0, b1)                                                \
    asm volatile("mma.sync.aligned.m16n8k16.row.col.f32.f16.f16.f32 "         \
                 "{%0,%1,%2,%3},{%4,%5,%6,%7},{%8,%9},{%0,%1,%2,%3};"         \
                 : "+f"((c)[0]), "+f"((c)[1]), "+f"((c)[2]), "+f"((c)[3])     \
                 : "r"((a)[0]), "r"((a)[1]), "r"((a)[2]), "r"((a)[3]),        \
                   "r"(b0), "r"(b1))

// ------------------- fused pool + window (block per (b,w)) -------------------
__global__ __launch_bounds__(128) void prep_kernel(const float* __restrict__ x,
                                                   h16* __restrict__ Ahi) {
    __shared__ float xs[4][512];
    const int w = blockIdx.x & 1023, b = blockIdx.x >> 10;
    const int hh = w >> 5, wh = w & 31;
    const int tid = threadIdx.x;
    const int tok0 = (hh * 2) * 64 + wh * 2;
    const float* xb = x + ((size_t)b * 4096) * 512;
    const int toks[4] = {tok0, tok0 + 1, tok0 + 64, tok0 + 65};
#pragma unroll
    for (int s = 0; s < 4; ++s) {
        const float4* src = (const float4*)(xb + (size_t)toks[s] * 512);
        *(float4*)&xs[s][tid * 4] = src[tid];
    }
    __syncthreads();
    {
        int c = tid * 4;
        float4 a = *(float4*)&xs[0][c];
        float4 b2 = *(float4*)&xs[1][c];
        float4 c2 = *(float4*)&xs[2][c];
        float4 d2 = *(float4*)&xs[3][c];
        float4 v = {0.25f * (a.x + b2.x + c2.x + d2.x),
                    0.25f * (a.y + b2.y + c2.y + d2.y),
                    0.25f * (a.z + b2.z + c2.z + d2.z),
                    0.25f * (a.w + b2.w + c2.w + d2.w)};
        round4_store(v, Ahi, (size_t)(b * 1024 + w) * 512 + c);
    }
#pragma unroll
    for (int t = 0; t < 4; ++t) {
        int u = tid;
        float4 v = {xs[0][t * 128 + u], xs[1][t * 128 + u],
                    xs[2][t * 128 + u], xs[3][t * 128 + u]};
        size_t wrow = (size_t)(8192 + (b * 1024 + w) * 4 + t) * 512;
        round4_store(v, Ahi, wrow + u * 4);
    }
}

// ------------------- weight round (fp16, vectorized) -------------------------
__global__ __launch_bounds__(256) void round_kernel(const float* __restrict__ src,
                                                    h16* __restrict__ hi, int n4) {
    int g = blockIdx.x * 256 + threadIdx.x;
    if (g >= n4) return;
    float4 v = ((const float4*)src)[g];
    round4_store(v, hi, (size_t)g * 4);
}

// ---- fp16 single-product HMMA GEMM (K=512), 4 warps (2x2), 64x64 tiles ------
#define GEMM_SMEM (2 * 16384 + 1024)

__global__ __launch_bounds__(128) void gemm_mma(
    const h16* __restrict__ Ah, const h16* __restrict__ Bh,
    const float* __restrict__ bias, float* __restrict__ C,
    h16* __restrict__ Ch, int N, int mode,
    h16* __restrict__ Qh, h16* __restrict__ Ql,
    h16* __restrict__ Kh, h16* __restrict__ Vh) {
    extern __shared__ char dynsm[];
    const int tid = threadIdx.x;
    const int wid = tid >> 5, lane = tid & 31;
    const int wm = wid & 1, wn = wid >> 1;              // 2 x 2 warp grid
    const size_t bm = (size_t)blockIdx.y * 128;
    const size_t bn = (size_t)blockIdx.x * 128;
    const uint32_t sb = (smem_u32(dynsm) + 1023) & ~1023u;

    const char* srcA = (const char*)(Ah + bm * 512);
    const char* srcB = (const char*)(Bh + bn * 512);

    auto load_chunk = [&](int kc, int s) {
        const uint32_t base = sb + s * 16384;
#pragma unroll
        for (int j = 0; j < 4; ++j) {
            uint32_t u = tid + j * 128;
            uint32_t r = u >> 2, c16 = u & 3;
            cp16(base + sw128(u * 16),
                 srcA + (size_t)r * 1024 + kc * 64 + c16 * 16);
            cp16(base + 8192 + sw128(u * 16),
                 srcB + (size_t)r * 1024 + kc * 64 + c16 * 16);
        }
        asm volatile("cp.async.commit_group;" ::: "memory");
    };

    float c[4][8][4];
#pragma unroll
    for (int i = 0; i < 4; ++i)
#pragma unroll
        for (int j = 0; j < 8; ++j)
#pragma unroll
            for (int q = 0; q < 4; ++q) c[i][j][q] = 0.f;

    const int sub = lane >> 3;
    const int rowl = ((sub & 1) << 3) + (lane & 7);
    const int csel = sub >> 1;

    load_chunk(0, 0);
    load_chunk(1, 1);

#pragma unroll 1
    for (int kc = 0; kc < 16; ++kc) {
        const int s = kc & 1;
        if (kc < 15) asm volatile("cp.async.wait_group 1;" ::: "memory");
        else         asm volatile("cp.async.wait_group 0;" ::: "memory");
        __syncthreads();
        const uint32_t st = sb + s * 16384;

#pragma unroll
        for (int kk = 0; kk < 2; ++kk) {
            uint32_t bh4[2][4];
            {
                uint32_t off = (uint32_t)(wn * 64 + rowl) * 64 +
                               (uint32_t)(kk * 2 + csel) * 16;
                LDSM4(bh4[0], st + 8192 + sw128(off));
            }
            uint32_t ah[4][4];
#pragma unroll
            for (int mt = 0; mt < 4; ++mt) {
                uint32_t off = (uint32_t)(wm * 64 + mt * 16 + rowl) * 64 +
                               (uint32_t)(kk * 2 + csel) * 16;
                LDSM4(ah[mt], st + sw128(off));
            }
#pragma unroll
            for (int nb = 0; nb < 4; ++nb) {
                const int p = nb & 1;
                if (nb < 3) {
                    uint32_t off = (uint32_t)(wn * 64 + (nb + 1) * 16 + rowl) * 64 +
                                   (uint32_t)(kk * 2 + csel) * 16;
                    LDSM4(bh4[p ^ 1], st + 8192 + sw128(off));
                }
#pragma unroll
                for (int mt = 0; mt < 4; ++mt) {
                    MMA16816(c[mt][nb * 2], ah[mt], bh4[p][0], bh4[p][2]);
                    MMA16816(c[mt][nb * 2 + 1], ah[mt], bh4[p][1], bh4[p][3]);
                }
            }
        }
        __syncthreads();
        if (kc + 2 < 16) load_chunk(kc + 2, s);
    }

    const int r0 = lane >> 2;
    const int c0 = (lane & 3) * 2;
    if (mode == 1 && bm < 8192) {
#pragma unroll
        for (int mt = 0; mt < 4; ++mt)
#pragma unroll
            for (int n8 = 0; n8 < 8; ++n8) {
                int col = (int)bn + wn * 64 + n8 * 8 + c0;
                int which = col >> 9, jj = col & 511;
                int h = jj >> 6, d = jj & 63;
#pragma unroll
                for (int half = 0; half < 2; ++half) {
                    int row = (int)bm + wm * 64 + mt * 16 + r0 + half * 8;
                    int b = row >> 10, tok = row & 1023;
                    size_t dst = ((size_t)((b * 8 + h) * 1024 + tok)) * 64 + d;
                    float v0 = c[mt][n8][half * 2], v1 = c[mt][n8][half * 2 + 1];
                    if (which == 0) {
                        uint32_t hu, lu;
                        pack_split_h(v0 * 0.125f, v1 * 0.125f, &hu, &lu);
                        *(uint32_t*)(Qh + dst) = hu;
                        *(uint32_t*)(Ql + dst) = lu;
                    } else if (which == 1) {
                        *(uint32_t*)(Kh + dst) = pack_round_h(v0, v1);
                    } else {
                        *(uint32_t*)(Vh + dst) = pack_round_h(v0, v1);
                    }
                }
            }
    } else if (mode == 1) {
#pragma unroll
        for (int mt = 0; mt < 4; ++mt)
#pragma unroll
            for (int n8 = 0; n8 < 8; ++n8) {
                size_t row = bm + wm * 64 + mt * 16 + r0;
                size_t col = bn + wn * 64 + n8 * 8 + c0;
                *(uint32_t*)(Ch + row * 1536 + col) =
                    pack_round_h(c[mt][n8][0], c[mt][n8][1]);
                *(uint32_t*)(Ch + (row + 8) * 1536 + col) =
                    pack_round_h(c[mt][n8][2], c[mt][n8][3]);
            }
    } else {
#pragma unroll
        for (int mt = 0; mt < 4; ++mt)
#pragma unroll
            for (int n8 = 0; n8 < 8; ++n8) {
                size_t row = bm + wm * 64 + mt * 16 + r0;
                size_t col = bn + wn * 64 + n8 * 8 + c0;
                float bx = bias[col], by = bias[col + 1];
                float2 v0 = {c[mt][n8][0] + bx, c[mt][n8][1] + by};
                float2 v1 = {c[mt][n8][2] + bx, c[mt][n8][3] + by};
                *(float2*)(C + row * (size_t)N + col) = v0;
                *(float2*)(C + (row + 8) * (size_t)N + col) = v1;
            }
    }
}

// ------------------- fp16 HMMA flash attention (hi branch) -------------------
#define ATT_SMEM (2 * 16384 + 1024)

__global__ __launch_bounds__(128) void hi_attn_mma(
    const h16* __restrict__ Qh, const h16* __restrict__ Ql,
    const h16* __restrict__ Kh, const h16* __restrict__ Vh,
    float* __restrict__ out) {
    extern __shared__ char dynsm[];
    const int tid = threadIdx.x;
    const int wid = tid >> 5, lane = tid & 31;
    const int qt = blockIdx.x, h = blockIdx.y, b = blockIdx.z;
    const uint32_t sb = (smem_u32(dynsm) + 1023) & ~1023u;
    const size_t bh = (size_t)(b * 8 + h) * 65536;

    const int sub = lane >> 3;
    const int rowl = ((sub & 1) << 3) + (lane & 7);
    const int csel = sub >> 1;

    {
        const char* qh_src = (const char*)(Qh + bh + (size_t)qt * 64 * 64);
        const char* ql_src = (const char*)(Ql + bh + (size_t)qt * 64 * 64);
#pragma unroll
        for (int u = tid; u < 512; u += 128) {
            cp16(sb + sw128(u * 16), qh_src + u * 16);
            cp16(sb + 8192 + sw128(u * 16), ql_src + u * 16);
        }
        asm volatile("cp.async.commit_group;" ::: "memory");
        asm volatile("cp.async.wait_group 0;" ::: "memory");
        __syncthreads();
    }
    uint32_t qh[4][4], ql[4][4];
#pragma unroll
    for (int kf = 0; kf < 4; ++kf) {
        uint32_t off = (uint32_t)(wid * 16 + rowl) * 128 + kf * 32 + csel * 16;
        LDSM4(qh[kf], sb + sw128(off));
        LDSM4(ql[kf], sb + 8192 + sw128(off));
    }
    __syncthreads();

    const char* kh_src = (const char*)(Kh + bh);
    const char* vh_src = (const char*)(Vh + bh);

    auto load_kv = [&](int kt, int s) {
        const uint32_t base = sb + s * 16384;
        const size_t go = (size_t)kt * 8192;
#pragma unroll
        for (int u = tid; u < 512; u += 128) {
            uint32_t sw = sw128(u * 16);
            cp16(base + sw, kh_src + go + u * 16);
            cp16(base + 8192 + sw, vh_src + go + u * 16);
        }
        asm volatile("cp.async.commit_group;" ::: "memory");
    };

    load_kv(0, 0);
    load_kv(1, 1);

    float o[8][4];
#pragma unroll
    for (int i = 0; i < 8; ++i)
#pragma unroll
        for (int j = 0; j < 4; ++j) o[i][j] = 0.f;
    float m0 = -1e30f, m1 = -1e30f, l0 = 0.f, l1 = 0.f;

#pragma unroll 1
    for (int kt = 0; kt < 16; ++kt) {
        const int s = kt & 1;
        if (kt < 15) asm volatile("cp.async.wait_group 1;" ::: "memory");
        else         asm volatile("cp.async.wait_group 0;" ::: "memory");
        __syncthreads();
        const uint32_t base = sb + s * 16384;

        float sfr[8][4];
#pragma unroll
        for (int i = 0; i < 8; ++i)
#pragma unroll
            for (int j = 0; j < 4; ++j) sfr[i][j] = 0.f;

#pragma unroll
        for (int kf = 0; kf < 4; ++kf) {
            uint32_t kbh[4][4];
#pragma unroll
            for (int nb = 0; nb < 4; ++nb) {
                uint32_t off = (uint32_t)(nb * 16 + rowl) * 128 + kf * 32 + csel * 16;
                LDSM4(kbh[nb], base + sw128(off));
            }
#pragma unroll
            for (int nb = 0; nb < 4; ++nb) {
                MMA16816(sfr[nb * 2], qh[kf], kbh[nb][0], kbh[nb][2]);
                MMA16816(sfr[nb * 2 + 1], qh[kf], kbh[nb][1], kbh[nb][3]);
            }
#pragma unroll
            for (int nb = 0; nb < 4; ++nb) {
                MMA16816(sfr[nb * 2], ql[kf], kbh[nb][0], kbh[nb][2]);
                MMA16816(sfr[nb * 2 + 1], ql[kf], kbh[nb][1], kbh[nb][3]);
            }
        }

        float mx0 = -1e30f, mx1 = -1e30f;
#pragma unroll
        for (int n8 = 0; n8 < 8; ++n8) {
            mx0 = fmaxf(mx0, fmaxf(sfr[n8][0], sfr[n8][1]));
            mx1 = fmaxf(mx1, fmaxf(sfr[n8][2], sfr[n8][3]));
        }
        mx0 = fmaxf(mx0, __shfl_xor_sync(0xffffffffu, mx0, 1));
        mx0 = fmaxf(mx0, __shfl_xor_sync(0xffffffffu, mx0, 2));
        mx1 = fmaxf(mx1, __shfl_xor_sync(0xffffffffu, mx1, 1));
        mx1 = fmaxf(mx1, __shfl_xor_sync(0xffffffffu, mx1, 2));
        float m0n = fmaxf(m0, mx0), m1n = fmaxf(m1, mx1);
        float c0 = __expf(m0 - m0n), c1 = __expf(m1 - m1n);
        m0 = m0n; m1 = m1n;
        float s0 = 0.f, s1 = 0.f;
#pragma unroll
        for (int n8 = 0; n8 < 8; ++n8) {
            sfr[n8][0] = __expf(sfr[n8][0] - m0n);
            sfr[n8][1] = __expf(sfr[n8][1] - m0n);
            sfr[n8][2] = __expf(sfr[n8][2] - m1n);
            sfr[n8][3] = __expf(sfr[n8][3] - m1n);
            s0 += sfr[n8][0] + sfr[n8][1];
            s1 += sfr[n8][2] + sfr[n8][3];
        }
        s0 += __shfl_xor_sync(0xffffffffu, s0, 1);
        s0 += __shfl_xor_sync(0xffffffffu, s0, 2);
        s1 += __shfl_xor_sync(0xffffffffu, s1, 1);
        s1 += __shfl_xor_sync(0xffffffffu, s1, 2);
        l0 = l0 * c0 + s0;
        l1 = l1 * c1 + s1;
#pragma unroll
        for (int n8 = 0; n8 < 8; ++n8) {
            o[n8][0] *= c0; o[n8][1] *= c0;
            o[n8][2] *= c1; o[n8][3] *= c1;
        }

#pragma unroll
        for (int kf = 0; kf < 4; ++kf) {
            uint32_t ah4[4], al4[4];
            pack_split_h(sfr[2 * kf][0], sfr[2 * kf][1], &ah4[0], &al4[0]);
            pack_split_h(sfr[2 * kf][2], sfr[2 * kf][3], &ah4[1], &al4[1]);
            pack_split_h(sfr[2 * kf + 1][0], sfr[2 * kf + 1][1], &ah4[2], &al4[2]);
            pack_split_h(sfr[2 * kf + 1][2], sfr[2 * kf + 1][3], &ah4[3], &al4[3]);
            uint32_t vbh[4][4];
#pragma unroll
            for (int dd = 0; dd < 4; ++dd) {
                uint32_t off = (uint32_t)(kf * 16 + rowl) * 128 + dd * 32 + csel * 16;
                LDSM4T(vbh[dd], base + 8192 + sw128(off));
            }
#pragma unroll
            for (int dd = 0; dd < 4; ++dd) {
                MMA16816(o[dd * 2], ah4, vbh[dd][0], vbh[dd][1]);
                MMA16816(o[dd * 2 + 1], ah4, vbh[dd][2], vbh[dd][3]);
            }
#pragma unroll
            for (int dd = 0; dd < 4; ++dd) {
                MMA16816(o[dd * 2], al4, vbh[dd][0], vbh[dd][1]);
                MMA16816(o[dd * 2 + 1], al4, vbh[dd][2], vbh[dd][3]);
            }
        }
        __syncthreads();
        if (kt + 2 < 16) load_kv(kt + 2, s);
    }

    float inv0 = 1.0f / l0, inv1 = 1.0f / l1;
    int r0 = lane >> 2, cc = (lane & 3) * 2;
    size_t row = (size_t)(b * 1024 + qt * 64 + wid * 16 + r0);
#pragma unroll
    for (int n8 = 0; n8 < 8; ++n8) {
        size_t col = h * 64 + n8 * 8 + cc;
        float2 v0 = {o[n8][0] * inv0, o[n8][1] * inv0};
        float2 v1 = {o[n8][2] * inv1, o[n8][3] * inv1};
        *(float2*)(out + row * 512 + col) = v0;
        *(float2*)(out + (row + 8) * 512 + col) = v1;
    }
}

// ------- fused lo attention + bilinear upsample + add -> fp16 Phi ------------
__global__ __launch_bounds__(256) void lo_fused_kernel(const h16* __restrict__ qkv,
                                                       const float* __restrict__ ahi,
                                                       h16* __restrict__ ph) {
    int gw = (blockIdx.x * 256 + threadIdx.x) >> 5;
    int lane = threadIdx.x & 31;
    int h = gw & 7;
    int w = (gw >> 3) & 1023;
    int b = gw >> 13;
    const h16* base = qkv + (size_t)(b * 4096 + w * 4) * 1536 + h * 64 + lane;
    float q[4][2], k[4][2], v[4][2];
#pragma unroll
    for (int t = 0; t < 4; ++t) {
        const h16* r = base + t * 1536;
        q[t][0] = __half2float(r[0]);    q[t][1] = __half2float(r[32]);
        k[t][0] = __half2float(r[512]);  k[t][1] = __half2float(r[544]);
        v[t][0] = __half2float(r[1024]); v[t][1] = __half2float(r[1056]);
    }
    float lg[4][4];
#pragma unroll
    for (int t = 0; t < 4; ++t)
#pragma unroll
        for (int s2 = 0; s2 < 4; ++s2)
            lg[t][s2] = q[t][0] * k[s2][0] + q[t][1] * k[s2][1];
#pragma unroll
    for (int off = 16; off; off >>= 1)
#pragma unroll
        for (int t = 0; t < 4; ++t)
#pragma unroll
            for (int s2 = 0; s2 < 4; ++s2)
                lg[t][s2] += __shfl_xor_sync(0xffffffffu, lg[t][s2], off);

    int hh = w >> 5, wh = w & 31;
    int c = h * 64 + lane;
    const float* hp = ahi + (size_t)b * 1024 * 512;
#pragma unroll
    for (int t = 0; t < 4; ++t) {
        float L0 = lg[t][0] * 0.125f, L1 = lg[t][1] * 0.125f;
        float L2 = lg[t][2] * 0.125f, L3 = lg[t][3] * 0.125f;
        float m = fmaxf(fmaxf(L0, L1), fmaxf(L2, L3));
        float p0 = __expf(L0 - m), p1 = __expf(L1 - m);
        float p2 = __expf(L2 - m), p3 = __expf(L3 - m);
        float inv = 1.0f / (p0 + p1 + p2 + p3);
        float o0 = (p0 * v[0][0] + p1 * v[1][0] + p2 * v[2][0] + p3 * v[3][0]) * inv;
        float o1 = (p0 * v[0][1] + p1 * v[1][1] + p2 * v[2][1] + p3 * v[3][1]) * inv;

        int y = hh * 2 + (t >> 1), x = wh * 2 + (t & 1);
        float fy = 0.5f * y - 0.25f;
        float fx = 0.5f * x - 0.25f;
        int y0 = (int)floorf(fy), x0 = (int)floorf(fx);
        float wy = fy - (float)y0, wx = fx - (float)x0;
        int y0c = max(y0, 0), y1c = min(y0 + 1, 31);
        int x0c = max(x0, 0), x1c = min(x0 + 1, 31);
        float w00 = (1.f - wy) * (1.f - wx), w01 = (1.f - wy) * wx;
        float w10 = wy * (1.f - wx), w11 = wy * wx;
        size_t p00 = (size_t)(y0c * 32 + x0c) * 512;
        size_t p01 = (size_t)(y0c * 32 + x1c) * 512;
        size_t p10 = (size_t)(y1c * 32 + x0c) * 512;
        size_t p11 = (size_t)(y1c * 32 + x1c) * 512;
        float u0 = w00 * hp[p00 + c] + w01 * hp[p01 + c] +
                   w10 * hp[p10 + c] + w11 * hp[p11 + c];
        float u1 = w00 * hp[p00 + c + 32] + w01 * hp[p01 + c + 32] +
                   w10 * hp[p10 + c + 32] + w11 * hp[p11 + c + 32];

        int tok = y * 64 + x;
        h16* op = ph + (size_t)(b * 4096 + tok) * 512 + c;
        op[0] = __float2half_rn(o0 + u0);
        op[32] = __float2half_rn(o1 + u1);
    }
}

// --------------------------------- launch -----------------------------------
extern "C" void kernel_launch(void* const* d_in, const int* in_sizes, int n_in,
                              void* d_out, int out_size) {
    const float* x     = (const float*)d_in[0];
    const float* Wqkv  = (const float*)d_in[1];
    const float* Wproj = (const float*)d_in[2];
    const float* bproj = (const float*)d_in[3];
    float* out = (float*)d_out;

    h16 *Ahi, *Wqh, *Wph, *Phi, *Qh, *Ql, *Kh, *Vh, *qcat;
    float *ahi;
    cudaGetSymbolAddress((void**)&Ahi, g_Ahi);
    cudaGetSymbolAddress((void**)&Wqh, g_Wqh);
    cudaGetSymbolAddress((void**)&Wph, g_Wph);
    cudaGetSymbolAddress((void**)&Phi, g_Phi);
    cudaGetSymbolAddress((void**)&qcat, g_qcat);
    cudaGetSymbolAddress((void**)&ahi, g_ahi);
    cudaGetSymbolAddress((void**)&Qh, g_Qh);
    cudaGetSymbolAddress((void**)&Ql, g_Ql);
    cudaGetSymbolAddress((void**)&Kh, g_Kh);
    cudaGetSymbolAddress((void**)&Vh, g_Vh);

    cudaFuncSetAttribute((const void*)gemm_mma,
                         cudaFuncAttributeMaxDynamicSharedMemorySize, GEMM_SMEM);
    cudaFuncSetAttribute((const void*)hi_attn_mma,
                         cudaFuncAttributeMaxDynamicSharedMemorySize, ATT_SMEM);

    prep_kernel<<<8192, 128>>>(x, Ahi);
    round_kernel<<<768, 256>>>(Wqkv, Wqh, 1536 * 512 / 4);
    round_kernel<<<256, 256>>>(Wproj, Wph, 512 * 512 / 4);

    gemm_mma<<<dim3(12, 320), 128, GEMM_SMEM>>>(Ahi, Wqh, nullptr, nullptr,
                                                qcat, 1536, 1, Qh, Ql, Kh, Vh);

    hi_attn_mma<<<dim3(16, 8, 8), 128, ATT_SMEM>>>(Qh, Ql, Kh, Vh, ahi);
    lo_fused_kernel<<<8192, 256>>>(qcat + (size_t)8192 * 1536, ahi, Phi);

    gemm_mma<<<dim3(4, 256), 128, GEMM_SMEM>>>(Phi, Wph, bproj, out, nullptr,
                                               512, 0,
                                               nullptr, nullptr, nullptr, nullptr);
}

// round 15
// speedup vs baseline: 1.1213x; 1.1213x over previous
#include <cuda_runtime.h>
#include <cuda_fp16.h>
#include <math.h>
#include <stdint.h>

typedef __half h16;

// ---------------------------------------------------------------------------
// HiLoAttention: B=8, N=4096 (64x64), C=512, heads=8, hd=64, window=2
// Round 15: GEMM = R13 config (256 thr, 64x32 warp tiles) with K-chunk
// doubled to 64 elems (128B rows, 8 chunks) to amortize per-sync overhead.
// ---------------------------------------------------------------------------

__device__ h16   g_Ahi[40960ull * 512];
__device__ h16   g_Wqh[1536 * 512];
__device__ h16   g_Wph[512 * 512];
__device__ h16   g_qcat[40960ull * 1536];     // only lo rows (>=8192) used
__device__ float g_ahi[8 * 1024 * 512];
__device__ h16   g_Phi[32768ull * 512];
__device__ h16   g_Qh[8 * 8 * 1024 * 64];
__device__ h16   g_Ql[8 * 8 * 1024 * 64];
__device__ h16   g_Kh[8 * 8 * 1024 * 64];
__device__ h16   g_Vh[8 * 8 * 1024 * 64];

// ------------------------------ helpers -------------------------------------
__device__ __forceinline__ uint32_t smem_u32(const void* p) {
    uint32_t a;
    asm("{ .reg .u64 t; cvta.to.shared.u64 t, %1; cvt.u32.u64 %0, t; }"
        : "=r"(a) : "l"(p));
    return a;
}
__device__ __forceinline__ void cp16(uint32_t dst, const void* src) {
    asm volatile("cp.async.cg.shared.global [%0], [%1], 16;"
                 :: "r"(dst), "l"(src) : "memory");
}
__device__ __forceinline__ uint32_t sw128(uint32_t off) {
    return off ^ ((off >> 3) & 0x70);
}
__device__ __forceinline__ void pack_split_h(float p0, float p1,
                                             uint32_t* hi, uint32_t* lo) {
    __half2 h2 = __floats2half2_rn(p0, p1);
    float2 f = __half22float2(h2);
    __half2 l2 = __floats2half2_rn(p0 - f.x, p1 - f.y);
    *hi = *(uint32_t*)&h2;
    *lo = *(uint32_t*)&l2;
}
__device__ __forceinline__ uint32_t pack_round_h(float p0, float p1) {
    __half2 h2 = __floats2half2_rn(p0, p1);
    return *(uint32_t*)&h2;
}
__device__ __forceinline__ void round4_store(float4 v, h16* H, size_t off) {
    uint2 o = make_uint2(pack_round_h(v.x, v.y), pack_round_h(v.z, v.w));
    *(uint2*)(H + off) = o;
}

#define LDSM4(r, addr)                                                        \
    asm volatile("ldmatrix.sync.aligned.m8n8.x4.shared.b16 {%0,%1,%2,%3}, [%4];" \
                 : "=r"((r)[0]), "=r"((r)[1]), "=r"((r)[2]), "=r"((r)[3])     \
                 : "r"(addr))

#define LDSM4T(r, addr)                                                       \
    asm volatile("ldmatrix.sync.aligned.m8n8.x4.trans.shared.b16 {%0,%1,%2,%3}, [%4];" \
                 : "=r"((r)[0]), "=r"((r)[1]), "=r"((r)[2]), "=r"((r)[3])     \
                 : "r"(addr))

#define MMA16816(c, a, b0, b1)                                                \
    asm volatile("mma.sync.aligned.m16n8k16.row.col.f32.f16.f16.f32 "         \
                 "{%0,%1,%2,%3},{%4,%5,%6,%7},{%8,%9},{%0,%1,%2,%3};"         \
                 : "+f"((c)[0]), "+f"((c)[1]), "+f"((c)[2]), "+f"((c)[3])     \
                 : "r"((a)[0]), "r"((a)[1]), "r"((a)[2]), "r"((a)[3]),        \
                   "r"(b0), "r"(b1))

// ------------------- fused pool + window (block per (b,w)) -------------------
__global__ __launch_bounds__(128) void prep_kernel(const float* __restrict__ x,
                                                   h16* __restrict__ Ahi) {
    __shared__ float xs[4][512];
    const int w = blockIdx.x & 1023, b = blockIdx.x >> 10;
    const int hh = w >> 5, wh = w & 31;
    const int tid = threadIdx.x;
    const int tok0 = (hh * 2) * 64 + wh * 2;
    const float* xb = x + ((size_t)b * 4096) * 512;
    const int toks[4] = {tok0, tok0 + 1, tok0 + 64, tok0 + 65};
#pragma unroll
    for (int s = 0; s < 4; ++s) {
        const float4* src = (const float4*)(xb + (size_t)toks[s] * 512);
        *(float4*)&xs[s][tid * 4] = src[tid];
    }
    __syncthreads();
    {
        int c = tid * 4;
        float4 a = *(float4*)&xs[0][c];
        float4 b2 = *(float4*)&xs[1][c];
        float4 c2 = *(float4*)&xs[2][c];
        float4 d2 = *(float4*)&xs[3][c];
        float4 v = {0.25f * (a.x + b2.x + c2.x + d2.x),
                    0.25f * (a.y + b2.y + c2.y + d2.y),
                    0.25f * (a.z + b2.z + c2.z + d2.z),
                    0.25f * (a.w + b2.w + c2.w + d2.w)};
        round4_store(v, Ahi, (size_t)(b * 1024 + w) * 512 + c);
    }
#pragma unroll
    for (int t = 0; t < 4; ++t) {
        int u = tid;
        float4 v = {xs[0][t * 128 + u], xs[1][t * 128 + u],
                    xs[2][t * 128 + u], xs[3][t * 128 + u]};
        size_t wrow = (size_t)(8192 + (b * 1024 + w) * 4 + t) * 512;
        round4_store(v, Ahi, wrow + u * 4);
    }
}

// ------------------- weight round (fp16, vectorized) -------------------------
__global__ __launch_bounds__(256) void round_kernel(const float* __restrict__ src,
                                                    h16* __restrict__ hi, int n4) {
    int g = blockIdx.x * 256 + threadIdx.x;
    if (g >= n4) return;
    float4 v = ((const float4*)src)[g];
    round4_store(v, hi, (size_t)g * 4);
}

// ------ fp16 single-product HMMA GEMM (K=512), 8 warps, 64x32 warp tile ------
// K-chunk = 64 elems (128B rows), 8 chunks, 2-stage 32KB ring.
#define GEMM_SMEM (2 * 32768 + 1024)

__global__ __launch_bounds__(256) void gemm_mma(
    const h16* __restrict__ Ah, const h16* __restrict__ Bh,
    const float* __restrict__ bias, float* __restrict__ C,
    h16* __restrict__ Ch, int N, int mode,
    h16* __restrict__ Qh, h16* __restrict__ Ql,
    h16* __restrict__ Kh, h16* __restrict__ Vh) {
    extern __shared__ char dynsm[];
    const int tid = threadIdx.x;
    const int wid = tid >> 5, lane = tid & 31;
    const int wm = wid & 1, wn = wid >> 1;              // 2 x 4 warp grid
    const size_t bm = (size_t)blockIdx.y * 128;
    const size_t bn = (size_t)blockIdx.x * 128;
    const uint32_t sb = (smem_u32(dynsm) + 1023) & ~1023u;

    const char* srcA = (const char*)(Ah + bm * 512);
    const char* srcB = (const char*)(Bh + bn * 512);

    auto load_chunk = [&](int kc, int s) {
        const uint32_t base = sb + s * 32768;
#pragma unroll
        for (int j = 0; j < 4; ++j) {
            uint32_t u = tid + j * 256;                 // 1024 units of 16B
            uint32_t r = u >> 3, c8 = u & 7;
            cp16(base + sw128(u * 16),
                 srcA + (size_t)r * 1024 + kc * 128 + c8 * 16);
            cp16(base + 16384 + sw128(u * 16),
                 srcB + (size_t)r * 1024 + kc * 128 + c8 * 16);
        }
        asm volatile("cp.async.commit_group;" ::: "memory");
    };

    float c[4][4][4];
#pragma unroll
    for (int i = 0; i < 4; ++i)
#pragma unroll
        for (int j = 0; j < 4; ++j)
#pragma unroll
            for (int q = 0; q < 4; ++q) c[i][j][q] = 0.f;

    const int sub = lane >> 3;
    const int rowl = ((sub & 1) << 3) + (lane & 7);
    const int csel = sub >> 1;

    load_chunk(0, 0);
    load_chunk(1, 1);

#pragma unroll 1
    for (int kc = 0; kc < 8; ++kc) {
        const int s = kc & 1;
        if (kc < 7) asm volatile("cp.async.wait_group 1;" ::: "memory");
        else        asm volatile("cp.async.wait_group 0;" ::: "memory");
        __syncthreads();
        const uint32_t st = sb + s * 32768;

#pragma unroll
        for (int kk = 0; kk < 4; ++kk) {
            uint32_t bh4[2][4];
#pragma unroll
            for (int nb = 0; nb < 2; ++nb) {
                uint32_t off = (uint32_t)(wn * 32 + nb * 16 + rowl) * 128 +
                               (uint32_t)(kk * 2 + csel) * 16;
                LDSM4(bh4[nb], st + 16384 + sw128(off));
            }
            uint32_t ah[4][4];
#pragma unroll
            for (int mt = 0; mt < 4; ++mt) {
                uint32_t off = (uint32_t)(wm * 64 + mt * 16 + rowl) * 128 +
                               (uint32_t)(kk * 2 + csel) * 16;
                LDSM4(ah[mt], st + sw128(off));
            }
#pragma unroll
            for (int nb = 0; nb < 2; ++nb)
#pragma unroll
                for (int mt = 0; mt < 4; ++mt) {
                    MMA16816(c[mt][nb * 2], ah[mt], bh4[nb][0], bh4[nb][2]);
                    MMA16816(c[mt][nb * 2 + 1], ah[mt], bh4[nb][1], bh4[nb][3]);
                }
        }
        __syncthreads();
        if (kc + 2 < 8) load_chunk(kc + 2, s);
    }

    const int r0 = lane >> 2;
    const int c0 = (lane & 3) * 2;
    if (mode == 1 && bm < 8192) {
#pragma unroll
        for (int mt = 0; mt < 4; ++mt)
#pragma unroll
            for (int j = 0; j < 4; ++j) {
                int col = (int)bn + wn * 32 + j * 8 + c0;
                int which = col >> 9, jj = col & 511;
                int h = jj >> 6, d = jj & 63;
#pragma unroll
                for (int half = 0; half < 2; ++half) {
                    int row = (int)bm + wm * 64 + mt * 16 + r0 + half * 8;
                    int b = row >> 10, tok = row & 1023;
                    size_t dst = ((size_t)((b * 8 + h) * 1024 + tok)) * 64 + d;
                    float v0 = c[mt][j][half * 2], v1 = c[mt][j][half * 2 + 1];
                    if (which == 0) {
                        uint32_t hu, lu;
                        pack_split_h(v0 * 0.125f, v1 * 0.125f, &hu, &lu);
                        *(uint32_t*)(Qh + dst) = hu;
                        *(uint32_t*)(Ql + dst) = lu;
                    } else if (which == 1) {
                        *(uint32_t*)(Kh + dst) = pack_round_h(v0, v1);
                    } else {
                        *(uint32_t*)(Vh + dst) = pack_round_h(v0, v1);
                    }
                }
            }
    } else if (mode == 1) {
#pragma unroll
        for (int mt = 0; mt < 4; ++mt)
#pragma unroll
            for (int j = 0; j < 4; ++j) {
                size_t row = bm + wm * 64 + mt * 16 + r0;
                size_t col = bn + wn * 32 + j * 8 + c0;
                *(uint32_t*)(Ch + row * 1536 + col) =
                    pack_round_h(c[mt][j][0], c[mt][j][1]);
                *(uint32_t*)(Ch + (row + 8) * 1536 + col) =
                    pack_round_h(c[mt][j][2], c[mt][j][3]);
            }
    } else {
#pragma unroll
        for (int mt = 0; mt < 4; ++mt)
#pragma unroll
            for (int j = 0; j < 4; ++j) {
                size_t row = bm + wm * 64 + mt * 16 + r0;
                size_t col = bn + wn * 32 + j * 8 + c0;
                float bx = bias[col], by = bias[col + 1];
                float2 v0 = {c[mt][j][0] + bx, c[mt][j][1] + by};
                float2 v1 = {c[mt][j][2] + bx, c[mt][j][3] + by};
                *(float2*)(C + row * (size_t)N + col) = v0;
                *(float2*)(C + (row + 8) * (size_t)N + col) = v1;
            }
    }
}

// ------------------- fp16 HMMA flash attention (hi branch) -------------------
#define ATT_SMEM (2 * 16384 + 1024)

__global__ __launch_bounds__(128) void hi_attn_mma(
    const h16* __restrict__ Qh, const h16* __restrict__ Ql,
    const h16* __restrict__ Kh, const h16* __restrict__ Vh,
    float* __restrict__ out) {
    extern __shared__ char dynsm[];
    const int tid = threadIdx.x;
    const int wid = tid >> 5, lane = tid & 31;
    const int qt = blockIdx.x, h = blockIdx.y, b = blockIdx.z;
    const uint32_t sb = (smem_u32(dynsm) + 1023) & ~1023u;
    const size_t bh = (size_t)(b * 8 + h) * 65536;

    const int sub = lane >> 3;
    const int rowl = ((sub & 1) << 3) + (lane & 7);
    const int csel = sub >> 1;

    {
        const char* qh_src = (const char*)(Qh + bh + (size_t)qt * 64 * 64);
        const char* ql_src = (const char*)(Ql + bh + (size_t)qt * 64 * 64);
#pragma unroll
        for (int u = tid; u < 512; u += 128) {
            cp16(sb + sw128(u * 16), qh_src + u * 16);
            cp16(sb + 8192 + sw128(u * 16), ql_src + u * 16);
        }
        asm volatile("cp.async.commit_group;" ::: "memory");
        asm volatile("cp.async.wait_group 0;" ::: "memory");
        __syncthreads();
    }
    uint32_t qh[4][4], ql[4][4];
#pragma unroll
    for (int kf = 0; kf < 4; ++kf) {
        uint32_t off = (uint32_t)(wid * 16 + rowl) * 128 + kf * 32 + csel * 16;
        LDSM4(qh[kf], sb + sw128(off));
        LDSM4(ql[kf], sb + 8192 + sw128(off));
    }
    __syncthreads();

    const char* kh_src = (const char*)(Kh + bh);
    const char* vh_src = (const char*)(Vh + bh);

    auto load_kv = [&](int kt, int s) {
        const uint32_t base = sb + s * 16384;
        const size_t go = (size_t)kt * 8192;
#pragma unroll
        for (int u = tid; u < 512; u += 128) {
            uint32_t sw = sw128(u * 16);
            cp16(base + sw, kh_src + go + u * 16);
            cp16(base + 8192 + sw, vh_src + go + u * 16);
        }
        asm volatile("cp.async.commit_group;" ::: "memory");
    };

    load_kv(0, 0);
    load_kv(1, 1);

    float o[8][4];
#pragma unroll
    for (int i = 0; i < 8; ++i)
#pragma unroll
        for (int j = 0; j < 4; ++j) o[i][j] = 0.f;
    float m0 = -1e30f, m1 = -1e30f, l0 = 0.f, l1 = 0.f;

#pragma unroll 1
    for (int kt = 0; kt < 16; ++kt) {
        const int s = kt & 1;
        if (kt < 15) asm volatile("cp.async.wait_group 1;" ::: "memory");
        else         asm volatile("cp.async.wait_group 0;" ::: "memory");
        __syncthreads();
        const uint32_t base = sb + s * 16384;

        float sfr[8][4];
#pragma unroll
        for (int i = 0; i < 8; ++i)
#pragma unroll
            for (int j = 0; j < 4; ++j) sfr[i][j] = 0.f;

#pragma unroll
        for (int kf = 0; kf < 4; ++kf) {
            uint32_t kbh[4][4];
#pragma unroll
            for (int nb = 0; nb < 4; ++nb) {
                uint32_t off = (uint32_t)(nb * 16 + rowl) * 128 + kf * 32 + csel * 16;
                LDSM4(kbh[nb], base + sw128(off));
            }
#pragma unroll
            for (int nb = 0; nb < 4; ++nb) {
                MMA16816(sfr[nb * 2], qh[kf], kbh[nb][0], kbh[nb][2]);
                MMA16816(sfr[nb * 2 + 1], qh[kf], kbh[nb][1], kbh[nb][3]);
            }
#pragma unroll
            for (int nb = 0; nb < 4; ++nb) {
                MMA16816(sfr[nb * 2], ql[kf], kbh[nb][0], kbh[nb][2]);
                MMA16816(sfr[nb * 2 + 1], ql[kf], kbh[nb][1], kbh[nb][3]);
            }
        }

        float mx0 = -1e30f, mx1 = -1e30f;
#pragma unroll
        for (int n8 = 0; n8 < 8; ++n8) {
            mx0 = fmaxf(mx0, fmaxf(sfr[n8][0], sfr[n8][1]));
            mx1 = fmaxf(mx1, fmaxf(sfr[n8][2], sfr[n8][3]));
        }
        mx0 = fmaxf(mx0, __shfl_xor_sync(0xffffffffu, mx0, 1));
        mx0 = fmaxf(mx0, __shfl_xor_sync(0xffffffffu, mx0, 2));
        mx1 = fmaxf(mx1, __shfl_xor_sync(0xffffffffu, mx1, 1));
        mx1 = fmaxf(mx1, __shfl_xor_sync(0xffffffffu, mx1, 2));
        float m0n = fmaxf(m0, mx0), m1n = fmaxf(m1, mx1);
        float c0 = __expf(m0 - m0n), c1 = __expf(m1 - m1n);
        m0 = m0n; m1 = m1n;
        float s0 = 0.f, s1 = 0.f;
#pragma unroll
        for (int n8 = 0; n8 < 8; ++n8) {
            sfr[n8][0] = __expf(sfr[n8][0] - m0n);
            sfr[n8][1] = __expf(sfr[n8][1] - m0n);
            sfr[n8][2] = __expf(sfr[n8][2] - m1n);
            sfr[n8][3] = __expf(sfr[n8][3] - m1n);
            s0 += sfr[n8][0] + sfr[n8][1];
            s1 += sfr[n8][2] + sfr[n8][3];
        }
        s0 += __shfl_xor_sync(0xffffffffu, s0, 1);
        s0 += __shfl_xor_sync(0xffffffffu, s0, 2);
        s1 += __shfl_xor_sync(0xffffffffu, s1, 1);
        s1 += __shfl_xor_sync(0xffffffffu, s1, 2);
        l0 = l0 * c0 + s0;
        l1 = l1 * c1 + s1;
#pragma unroll
        for (int n8 = 0; n8 < 8; ++n8) {
            o[n8][0] *= c0; o[n8][1] *= c0;
            o[n8][2] *= c1; o[n8][3] *= c1;
        }

#pragma unroll
        for (int kf = 0; kf < 4; ++kf) {
            uint32_t ah4[4], al4[4];
            pack_split_h(sfr[2 * kf][0], sfr[2 * kf][1], &ah4[0], &al4[0]);
            pack_split_h(sfr[2 * kf][2], sfr[2 * kf][3], &ah4[1], &al4[1]);
            pack_split_h(sfr[2 * kf + 1][0], sfr[2 * kf + 1][1], &ah4[2], &al4[2]);
            pack_split_h(sfr[2 * kf + 1][2], sfr[2 * kf + 1][3], &ah4[3], &al4[3]);
            uint32_t vbh[4][4];
#pragma unroll
            for (int dd = 0; dd < 4; ++dd) {
                uint32_t off = (uint32_t)(kf * 16 + rowl) * 128 + dd * 32 + csel * 16;
                LDSM4T(vbh[dd], base + 8192 + sw128(off));
            }
#pragma unroll
            for (int dd = 0; dd < 4; ++dd) {
                MMA16816(o[dd * 2], ah4, vbh[dd][0], vbh[dd][1]);
                MMA16816(o[dd * 2 + 1], ah4, vbh[dd][2], vbh[dd][3]);
            }
#pragma unroll
            for (int dd = 0; dd < 4; ++dd) {
                MMA16816(o[dd * 2], al4, vbh[dd][0], vbh[dd][1]);
                MMA16816(o[dd * 2 + 1], al4, vbh[dd][2], vbh[dd][3]);
            }
        }
        __syncthreads();
        if (kt + 2 < 16) load_kv(kt + 2, s);
    }

    float inv0 = 1.0f / l0, inv1 = 1.0f / l1;
    int r0 = lane >> 2, cc = (lane & 3) * 2;
    size_t row = (size_t)(b * 1024 + qt * 64 + wid * 16 + r0);
#pragma unroll
    for (int n8 = 0; n8 < 8; ++n8) {
        size_t col = h * 64 + n8 * 8 + cc;
        float2 v0 = {o[n8][0] * inv0, o[n8][1] * inv0};
        float2 v1 = {o[n8][2] * inv1, o[n8][3] * inv1};
        *(float2*)(out + row * 512 + col) = v0;
        *(float2*)(out + (row + 8) * 512 + col) = v1;
    }
}

// ------- fused lo attention + bilinear upsample + add -> fp16 Phi ------------
__global__ __launch_bounds__(256) void lo_fused_kernel(const h16* __restrict__ qkv,
                                                       const float* __restrict__ ahi,
                                                       h16* __restrict__ ph) {
    int gw = (blockIdx.x * 256 + threadIdx.x) >> 5;
    int lane = threadIdx.x & 31;
    int h = gw & 7;
    int w = (gw >> 3) & 1023;
    int b = gw >> 13;
    const h16* base = qkv + (size_t)(b * 4096 + w * 4) * 1536 + h * 64 + lane;
    float q[4][2], k[4][2], v[4][2];
#pragma unroll
    for (int t = 0; t < 4; ++t) {
        const h16* r = base + t * 1536;
        q[t][0] = __half2float(r[0]);    q[t][1] = __half2float(r[32]);
        k[t][0] = __half2float(r[512]);  k[t][1] = __half2float(r[544]);
        v[t][0] = __half2float(r[1024]); v[t][1] = __half2float(r[1056]);
    }
    float lg[4][4];
#pragma unroll
    for (int t = 0; t < 4; ++t)
#pragma unroll
        for (int s2 = 0; s2 < 4; ++s2)
            lg[t][s2] = q[t][0] * k[s2][0] + q[t][1] * k[s2][1];
#pragma unroll
    for (int off = 16; off; off >>= 1)
#pragma unroll
        for (int t = 0; t < 4; ++t)
#pragma unroll
            for (int s2 = 0; s2 < 4; ++s2)
                lg[t][s2] += __shfl_xor_sync(0xffffffffu, lg[t][s2], off);

    int hh = w >> 5, wh = w & 31;
    int c = h * 64 + lane;
    const float* hp = ahi + (size_t)b * 1024 * 512;
#pragma unroll
    for (int t = 0; t < 4; ++t) {
        float L0 = lg[t][0] * 0.125f, L1 = lg[t][1] * 0.125f;
        float L2 = lg[t][2] * 0.125f, L3 = lg[t][3] * 0.125f;
        float m = fmaxf(fmaxf(L0, L1), fmaxf(L2, L3));
        float p0 = __expf(L0 - m), p1 = __expf(L1 - m);
        float p2 = __expf(L2 - m), p3 = __expf(L3 - m);
        float inv = 1.0f / (p0 + p1 + p2 + p3);
        float o0 = (p0 * v[0][0] + p1 * v[1][0] + p2 * v[2][0] + p3 * v[3][0]) * inv;
        float o1 = (p0 * v[0][1] + p1 * v[1][1] + p2 * v[2][1] + p3 * v[3][1]) * inv;

        int y = hh * 2 + (t >> 1), x = wh * 2 + (t & 1);
        float fy = 0.5f * y - 0.25f;
        float fx = 0.5f * x - 0.25f;
        int y0 = (int)floorf(fy), x0 = (int)floorf(fx);
        float wy = fy - (float)y0, wx = fx - (float)x0;
        int y0c = max(y0, 0), y1c = min(y0 + 1, 31);
        int x0c = max(x0, 0), x1c = min(x0 + 1, 31);
        float w00 = (1.f - wy) * (1.f - wx), w01 = (1.f - wy) * wx;
        float w10 = wy * (1.f - wx), w11 = wy * wx;
        size_t p00 = (size_t)(y0c * 32 + x0c) * 512;
        size_t p01 = (size_t)(y0c * 32 + x1c) * 512;
        size_t p10 = (size_t)(y1c * 32 + x0c) * 512;
        size_t p11 = (size_t)(y1c * 32 + x1c) * 512;
        float u0 = w00 * hp[p00 + c] + w01 * hp[p01 + c] +
                   w10 * hp[p10 + c] + w11 * hp[p11 + c];
        float u1 = w00 * hp[p00 + c + 32] + w01 * hp[p01 + c + 32] +
                   w10 * hp[p10 + c + 32] + w11 * hp[p11 + c + 32];

        int tok = y * 64 + x;
        h16* op = ph + (size_t)(b * 4096 + tok) * 512 + c;
        op[0] = __float2half_rn(o0 + u0);
        op[32] = __float2half_rn(o1 + u1);
    }
}

// --------------------------------- launch -----------------------------------
extern "C" void kernel_launch(void* const* d_in, const int* in_sizes, int n_in,
                              void* d_out, int out_size) {
    const float* x     = (const float*)d_in[0];
    const float* Wqkv  = (const float*)d_in[1];
    const float* Wproj = (const float*)d_in[2];
    const float* bproj = (const float*)d_in[3];
    float* out = (float*)d_out;

    h16 *Ahi, *Wqh, *Wph, *Phi, *Qh, *Ql, *Kh, *Vh, *qcat;
    float *ahi;
    cudaGetSymbolAddress((void**)&Ahi, g_Ahi);
    cudaGetSymbolAddress((void**)&Wqh, g_Wqh);
    cudaGetSymbolAddress((void**)&Wph, g_Wph);
    cudaGetSymbolAddress((void**)&Phi, g_Phi);
    cudaGetSymbolAddress((void**)&qcat, g_qcat);
    cudaGetSymbolAddress((void**)&ahi, g_ahi);
    cudaGetSymbolAddress((void**)&Qh, g_Qh);
    cudaGetSymbolAddress((void**)&Ql, g_Ql);
    cudaGetSymbolAddress((void**)&Kh, g_Kh);
    cudaGetSymbolAddress((void**)&Vh, g_Vh);

    cudaFuncSetAttribute((const void*)gemm_mma,
                         cudaFuncAttributeMaxDynamicSharedMemorySize, GEMM_SMEM);
    cudaFuncSetAttribute((const void*)hi_attn_mma,
                         cudaFuncAttributeMaxDynamicSharedMemorySize, ATT_SMEM);

    prep_kernel<<<8192, 128>>>(x, Ahi);
    round_kernel<<<768, 256>>>(Wqkv, Wqh, 1536 * 512 / 4);
    round_kernel<<<256, 256>>>(Wproj, Wph, 512 * 512 / 4);

    gemm_mma<<<dim3(12, 320), 256, GEMM_SMEM>>>(Ahi, Wqh, nullptr, nullptr,
                                                qcat, 1536, 1, Qh, Ql, Kh, Vh);

    hi_attn_mma<<<dim3(16, 8, 8), 128, ATT_SMEM>>>(Qh, Ql, Kh, Vh, ahi);
    lo_fused_kernel<<<8192, 256>>>(qcat + (size_t)8192 * 1536, ahi, Phi);

    gemm_mma<<<dim3(4, 256), 256, GEMM_SMEM>>>(Phi, Wph, bproj, out, nullptr,
                                               512, 0,
                                               nullptr, nullptr, nullptr, nullptr);
}

// round 16
// speedup vs baseline: 1.2111x; 1.0801x over previous
#include <cuda_runtime.h>
#include <cuda_fp16.h>
#include <math.h>
#include <stdint.h>

typedef __half h16;

// ---------------------------------------------------------------------------
// HiLoAttention: B=8, N=4096 (64x64), C=512, heads=8, hd=64, window=2
// Round 16: hi-attention drops compensation (single-product fp16 QK and PV;
// hi output is fp16-rounded at Phi anyway so compensation there was ~free of
// benefit). KV stage doubled to 128 keys (2 sub-tiles per sync). GEMMs as R15.
// ---------------------------------------------------------------------------

__device__ h16   g_Ahi[40960ull * 512];
__device__ h16   g_Wqh[1536 * 512];
__device__ h16   g_Wph[512 * 512];
__device__ h16   g_qcat[40960ull * 1536];     // only lo rows (>=8192) used
__device__ float g_ahi[8 * 1024 * 512];
__device__ h16   g_Phi[32768ull * 512];
__device__ h16   g_Qh[8 * 8 * 1024 * 64];
__device__ h16   g_Kh[8 * 8 * 1024 * 64];
__device__ h16   g_Vh[8 * 8 * 1024 * 64];

// ------------------------------ helpers -------------------------------------
__device__ __forceinline__ uint32_t smem_u32(const void* p) {
    uint32_t a;
    asm("{ .reg .u64 t; cvta.to.shared.u64 t, %1; cvt.u32.u64 %0, t; }"
        : "=r"(a) : "l"(p));
    return a;
}
__device__ __forceinline__ void cp16(uint32_t dst, const void* src) {
    asm volatile("cp.async.cg.shared.global [%0], [%1], 16;"
                 :: "r"(dst), "l"(src) : "memory");
}
__device__ __forceinline__ uint32_t sw128(uint32_t off) {
    return off ^ ((off >> 3) & 0x70);
}
__device__ __forceinline__ uint32_t pack_round_h(float p0, float p1) {
    __half2 h2 = __floats2half2_rn(p0, p1);
    return *(uint32_t*)&h2;
}
__device__ __forceinline__ void round4_store(float4 v, h16* H, size_t off) {
    uint2 o = make_uint2(pack_round_h(v.x, v.y), pack_round_h(v.z, v.w));
    *(uint2*)(H + off) = o;
}

#define LDSM4(r, addr)                                                        \
    asm volatile("ldmatrix.sync.aligned.m8n8.x4.shared.b16 {%0,%1,%2,%3}, [%4];" \
                 : "=r"((r)[0]), "=r"((r)[1]), "=r"((r)[2]), "=r"((r)[3])     \
                 : "r"(addr))

#define LDSM4T(r, addr)                                                       \
    asm volatile("ldmatrix.sync.aligned.m8n8.x4.trans.shared.b16 {%0,%1,%2,%3}, [%4];" \
                 : "=r"((r)[0]), "=r"((r)[1]), "=r"((r)[2]), "=r"((r)[3])     \
                 : "r"(addr))

#define MMA16816(c, a, b0, b1)                                                \
    asm volatile("mma.sync.aligned.m16n8k16.row.col.f32.f16.f16.f32 "         \
                 "{%0,%1,%2,%3},{%4,%5,%6,%7},{%8,%9},{%0,%1,%2,%3};"         \
                 : "+f"((c)[0]), "+f"((c)[1]), "+f"((c)[2]), "+f"((c)[3])     \
                 : "r"((a)[0]), "r"((a)[1]), "r"((a)[2]), "r"((a)[3]),        \
                   "r"(b0), "r"(b1))

// ------------------- fused pool + window (block per (b,w)) -------------------
__global__ __launch_bounds__(128) void prep_kernel(const float* __restrict__ x,
                                                   h16* __restrict__ Ahi) {
    __shared__ float xs[4][512];
    const int w = blockIdx.x & 1023, b = blockIdx.x >> 10;
    const int hh = w >> 5, wh = w & 31;
    const int tid = threadIdx.x;
    const int tok0 = (hh * 2) * 64 + wh * 2;
    const float* xb = x + ((size_t)b * 4096) * 512;
    const int toks[4] = {tok0, tok0 + 1, tok0 + 64, tok0 + 65};
#pragma unroll
    for (int s = 0; s < 4; ++s) {
        const float4* src = (const float4*)(xb + (size_t)toks[s] * 512);
        *(float4*)&xs[s][tid * 4] = src[tid];
    }
    __syncthreads();
    {
        int c = tid * 4;
        float4 a = *(float4*)&xs[0][c];
        float4 b2 = *(float4*)&xs[1][c];
        float4 c2 = *(float4*)&xs[2][c];
        float4 d2 = *(float4*)&xs[3][c];
        float4 v = {0.25f * (a.x + b2.x + c2.x + d2.x),
                    0.25f * (a.y + b2.y + c2.y + d2.y),
                    0.25f * (a.z + b2.z + c2.z + d2.z),
                    0.25f * (a.w + b2.w + c2.w + d2.w)};
        round4_store(v, Ahi, (size_t)(b * 1024 + w) * 512 + c);
    }
#pragma unroll
    for (int t = 0; t < 4; ++t) {
        int u = tid;
        float4 v = {xs[0][t * 128 + u], xs[1][t * 128 + u],
                    xs[2][t * 128 + u], xs[3][t * 128 + u]};
        size_t wrow = (size_t)(8192 + (b * 1024 + w) * 4 + t) * 512;
        round4_store(v, Ahi, wrow + u * 4);
    }
}

// ------------------- weight round (fp16, vectorized) -------------------------
__global__ __launch_bounds__(256) void round_kernel(const float* __restrict__ src,
                                                    h16* __restrict__ hi, int n4) {
    int g = blockIdx.x * 256 + threadIdx.x;
    if (g >= n4) return;
    float4 v = ((const float4*)src)[g];
    round4_store(v, hi, (size_t)g * 4);
}

// ------ fp16 single-product HMMA GEMM (K=512), 8 warps, 64x32 warp tile ------
// K-chunk = 64 elems (128B rows), 8 chunks, 2-stage 32KB ring.
#define GEMM_SMEM (2 * 32768 + 1024)

__global__ __launch_bounds__(256) void gemm_mma(
    const h16* __restrict__ Ah, const h16* __restrict__ Bh,
    const float* __restrict__ bias, float* __restrict__ C,
    h16* __restrict__ Ch, int N, int mode,
    h16* __restrict__ Qh, h16* __restrict__ Kh, h16* __restrict__ Vh) {
    extern __shared__ char dynsm[];
    const int tid = threadIdx.x;
    const int wid = tid >> 5, lane = tid & 31;
    const int wm = wid & 1, wn = wid >> 1;              // 2 x 4 warp grid
    const size_t bm = (size_t)blockIdx.y * 128;
    const size_t bn = (size_t)blockIdx.x * 128;
    const uint32_t sb = (smem_u32(dynsm) + 1023) & ~1023u;

    const char* srcA = (const char*)(Ah + bm * 512);
    const char* srcB = (const char*)(Bh + bn * 512);

    auto load_chunk = [&](int kc, int s) {
        const uint32_t base = sb + s * 32768;
#pragma unroll
        for (int j = 0; j < 4; ++j) {
            uint32_t u = tid + j * 256;                 // 1024 units of 16B
            uint32_t r = u >> 3, c8 = u & 7;
            cp16(base + sw128(u * 16),
                 srcA + (size_t)r * 1024 + kc * 128 + c8 * 16);
            cp16(base + 16384 + sw128(u * 16),
                 srcB + (size_t)r * 1024 + kc * 128 + c8 * 16);
        }
        asm volatile("cp.async.commit_group;" ::: "memory");
    };

    float c[4][4][4];
#pragma unroll
    for (int i = 0; i < 4; ++i)
#pragma unroll
        for (int j = 0; j < 4; ++j)
#pragma unroll
            for (int q = 0; q < 4; ++q) c[i][j][q] = 0.f;

    const int sub = lane >> 3;
    const int rowl = ((sub & 1) << 3) + (lane & 7);
    const int csel = sub >> 1;

    load_chunk(0, 0);
    load_chunk(1, 1);

#pragma unroll 1
    for (int kc = 0; kc < 8; ++kc) {
        const int s = kc & 1;
        if (kc < 7) asm volatile("cp.async.wait_group 1;" ::: "memory");
        else        asm volatile("cp.async.wait_group 0;" ::: "memory");
        __syncthreads();
        const uint32_t st = sb + s * 32768;

#pragma unroll
        for (int kk = 0; kk < 4; ++kk) {
            uint32_t bh4[2][4];
#pragma unroll
            for (int nb = 0; nb < 2; ++nb) {
                uint32_t off = (uint32_t)(wn * 32 + nb * 16 + rowl) * 128 +
                               (uint32_t)(kk * 2 + csel) * 16;
                LDSM4(bh4[nb], st + 16384 + sw128(off));
            }
            uint32_t ah[4][4];
#pragma unroll
            for (int mt = 0; mt < 4; ++mt) {
                uint32_t off = (uint32_t)(wm * 64 + mt * 16 + rowl) * 128 +
                               (uint32_t)(kk * 2 + csel) * 16;
                LDSM4(ah[mt], st + sw128(off));
            }
#pragma unroll
            for (int nb = 0; nb < 2; ++nb)
#pragma unroll
                for (int mt = 0; mt < 4; ++mt) {
                    MMA16816(c[mt][nb * 2], ah[mt], bh4[nb][0], bh4[nb][2]);
                    MMA16816(c[mt][nb * 2 + 1], ah[mt], bh4[nb][1], bh4[nb][3]);
                }
        }
        __syncthreads();
        if (kc + 2 < 8) load_chunk(kc + 2, s);
    }

    const int r0 = lane >> 2;
    const int c0 = (lane & 3) * 2;
    if (mode == 1 && bm < 8192) {
#pragma unroll
        for (int mt = 0; mt < 4; ++mt)
#pragma unroll
            for (int j = 0; j < 4; ++j) {
                int col = (int)bn + wn * 32 + j * 8 + c0;
                int which = col >> 9, jj = col & 511;
                int h = jj >> 6, d = jj & 63;
#pragma unroll
                for (int half = 0; half < 2; ++half) {
                    int row = (int)bm + wm * 64 + mt * 16 + r0 + half * 8;
                    int b = row >> 10, tok = row & 1023;
                    size_t dst = ((size_t)((b * 8 + h) * 1024 + tok)) * 64 + d;
                    float v0 = c[mt][j][half * 2], v1 = c[mt][j][half * 2 + 1];
                    if (which == 0) {
                        *(uint32_t*)(Qh + dst) =
                            pack_round_h(v0 * 0.125f, v1 * 0.125f);
                    } else if (which == 1) {
                        *(uint32_t*)(Kh + dst) = pack_round_h(v0, v1);
                    } else {
                        *(uint32_t*)(Vh + dst) = pack_round_h(v0, v1);
                    }
                }
            }
    } else if (mode == 1) {
#pragma unroll
        for (int mt = 0; mt < 4; ++mt)
#pragma unroll
            for (int j = 0; j < 4; ++j) {
                size_t row = bm + wm * 64 + mt * 16 + r0;
                size_t col = bn + wn * 32 + j * 8 + c0;
                *(uint32_t*)(Ch + row * 1536 + col) =
                    pack_round_h(c[mt][j][0], c[mt][j][1]);
                *(uint32_t*)(Ch + (row + 8) * 1536 + col) =
                    pack_round_h(c[mt][j][2], c[mt][j][3]);
            }
    } else {
#pragma unroll
        for (int mt = 0; mt < 4; ++mt)
#pragma unroll
            for (int j = 0; j < 4; ++j) {
                size_t row = bm + wm * 64 + mt * 16 + r0;
                size_t col = bn + wn * 32 + j * 8 + c0;
                float bx = bias[col], by = bias[col + 1];
                float2 v0 = {c[mt][j][0] + bx, c[mt][j][1] + by};
                float2 v1 = {c[mt][j][2] + bx, c[mt][j][3] + by};
                *(float2*)(C + row * (size_t)N + col) = v0;
                *(float2*)(C + (row + 8) * (size_t)N + col) = v1;
            }
    }
}

// ------------- fp16 HMMA flash attention (hi branch, uncompensated) ----------
// stage = 128 keys (2 x 64-key sub-tiles), 32KB; 2-stage ring; 8 stages.
#define ATT_SMEM (2 * 32768 + 1024)

__global__ __launch_bounds__(128) void hi_attn_mma(
    const h16* __restrict__ Qh, const h16* __restrict__ Kh,
    const h16* __restrict__ Vh, float* __restrict__ out) {
    extern __shared__ char dynsm[];
    const int tid = threadIdx.x;
    const int wid = tid >> 5, lane = tid & 31;
    const int qt = blockIdx.x, h = blockIdx.y, b = blockIdx.z;
    const uint32_t sb = (smem_u32(dynsm) + 1023) & ~1023u;
    const size_t bh = (size_t)(b * 8 + h) * 65536;

    const int sub = lane >> 3;
    const int rowl = ((sub & 1) << 3) + (lane & 7);
    const int csel = sub >> 1;

    {
        const char* qh_src = (const char*)(Qh + bh + (size_t)qt * 64 * 64);
#pragma unroll
        for (int u = tid; u < 512; u += 128)
            cp16(sb + sw128(u * 16), qh_src + u * 16);
        asm volatile("cp.async.commit_group;" ::: "memory");
        asm volatile("cp.async.wait_group 0;" ::: "memory");
        __syncthreads();
    }
    uint32_t qh[4][4];
#pragma unroll
    for (int kf = 0; kf < 4; ++kf) {
        uint32_t off = (uint32_t)(wid * 16 + rowl) * 128 + kf * 32 + csel * 16;
        LDSM4(qh[kf], sb + sw128(off));
    }
    __syncthreads();

    const char* kh_src = (const char*)(Kh + bh);
    const char* vh_src = (const char*)(Vh + bh);

    // stage layout: [K0 8K][V0 8K][K1 8K][V1 8K]
    auto load_kv = [&](int g, int s) {
        const uint32_t base = sb + s * 32768;
        const size_t go = (size_t)g * 16384;
#pragma unroll
        for (int half = 0; half < 2; ++half)
#pragma unroll
            for (int u = tid; u < 512; u += 128) {
                uint32_t sw = sw128(u * 16);
                cp16(base + half * 16384 + sw,
                     kh_src + go + half * 8192 + u * 16);
                cp16(base + half * 16384 + 8192 + sw,
                     vh_src + go + half * 8192 + u * 16);
            }
        asm volatile("cp.async.commit_group;" ::: "memory");
    };

    load_kv(0, 0);
    load_kv(1, 1);

    float o[8][4];
#pragma unroll
    for (int i = 0; i < 8; ++i)
#pragma unroll
        for (int j = 0; j < 4; ++j) o[i][j] = 0.f;
    float m0 = -1e30f, m1 = -1e30f, l0 = 0.f, l1 = 0.f;

#pragma unroll 1
    for (int stg = 0; stg < 8; ++stg) {
        const int s = stg & 1;
        if (stg < 7) asm volatile("cp.async.wait_group 1;" ::: "memory");
        else         asm volatile("cp.async.wait_group 0;" ::: "memory");
        __syncthreads();

#pragma unroll
        for (int half = 0; half < 2; ++half) {
            const uint32_t base = sb + s * 32768 + half * 16384;

            float sfr[8][4];
#pragma unroll
            for (int i = 0; i < 8; ++i)
#pragma unroll
                for (int j = 0; j < 4; ++j) sfr[i][j] = 0.f;

#pragma unroll
            for (int kf = 0; kf < 4; ++kf) {
                uint32_t kbh[4][4];
#pragma unroll
                for (int nb = 0; nb < 4; ++nb) {
                    uint32_t off = (uint32_t)(nb * 16 + rowl) * 128 +
                                   kf * 32 + csel * 16;
                    LDSM4(kbh[nb], base + sw128(off));
                }
#pragma unroll
                for (int nb = 0; nb < 4; ++nb) {
                    MMA16816(sfr[nb * 2], qh[kf], kbh[nb][0], kbh[nb][2]);
                    MMA16816(sfr[nb * 2 + 1], qh[kf], kbh[nb][1], kbh[nb][3]);
                }
            }

            float mx0 = -1e30f, mx1 = -1e30f;
#pragma unroll
            for (int n8 = 0; n8 < 8; ++n8) {
                mx0 = fmaxf(mx0, fmaxf(sfr[n8][0], sfr[n8][1]));
                mx1 = fmaxf(mx1, fmaxf(sfr[n8][2], sfr[n8][3]));
            }
            mx0 = fmaxf(mx0, __shfl_xor_sync(0xffffffffu, mx0, 1));
            mx0 = fmaxf(mx0, __shfl_xor_sync(0xffffffffu, mx0, 2));
            mx1 = fmaxf(mx1, __shfl_xor_sync(0xffffffffu, mx1, 1));
            mx1 = fmaxf(mx1, __shfl_xor_sync(0xffffffffu, mx1, 2));
            float m0n = fmaxf(m0, mx0), m1n = fmaxf(m1, mx1);
            float c0 = __expf(m0 - m0n), c1 = __expf(m1 - m1n);
            m0 = m0n; m1 = m1n;
            float s0 = 0.f, s1 = 0.f;
#pragma unroll
            for (int n8 = 0; n8 < 8; ++n8) {
                sfr[n8][0] = __expf(sfr[n8][0] - m0n);
                sfr[n8][1] = __expf(sfr[n8][1] - m0n);
                sfr[n8][2] = __expf(sfr[n8][2] - m1n);
                sfr[n8][3] = __expf(sfr[n8][3] - m1n);
                s0 += sfr[n8][0] + sfr[n8][1];
                s1 += sfr[n8][2] + sfr[n8][3];
            }
            s0 += __shfl_xor_sync(0xffffffffu, s0, 1);
            s0 += __shfl_xor_sync(0xffffffffu, s0, 2);
            s1 += __shfl_xor_sync(0xffffffffu, s1, 1);
            s1 += __shfl_xor_sync(0xffffffffu, s1, 2);
            l0 = l0 * c0 + s0;
            l1 = l1 * c1 + s1;
#pragma unroll
            for (int n8 = 0; n8 < 8; ++n8) {
                o[n8][0] *= c0; o[n8][1] *= c0;
                o[n8][2] *= c1; o[n8][3] *= c1;
            }

#pragma unroll
            for (int kf = 0; kf < 4; ++kf) {
                uint32_t ph4[4];
                ph4[0] = pack_round_h(sfr[2 * kf][0], sfr[2 * kf][1]);
                ph4[1] = pack_round_h(sfr[2 * kf][2], sfr[2 * kf][3]);
                ph4[2] = pack_round_h(sfr[2 * kf + 1][0], sfr[2 * kf + 1][1]);
                ph4[3] = pack_round_h(sfr[2 * kf + 1][2], sfr[2 * kf + 1][3]);
                uint32_t vbh[4][4];
#pragma unroll
                for (int dd = 0; dd < 4; ++dd) {
                    uint32_t off = (uint32_t)(kf * 16 + rowl) * 128 +
                                   dd * 32 + csel * 16;
                    LDSM4T(vbh[dd], base + 8192 + sw128(off));
                }
#pragma unroll
                for (int dd = 0; dd < 4; ++dd) {
                    MMA16816(o[dd * 2], ph4, vbh[dd][0], vbh[dd][1]);
                    MMA16816(o[dd * 2 + 1], ph4, vbh[dd][2], vbh[dd][3]);
                }
            }
        }
        __syncthreads();
        if (stg + 2 < 8) load_kv(stg + 2, s);
    }

    float inv0 = 1.0f / l0, inv1 = 1.0f / l1;
    int r0 = lane >> 2, cc = (lane & 3) * 2;
    size_t row = (size_t)(b * 1024 + qt * 64 + wid * 16 + r0);
#pragma unroll
    for (int n8 = 0; n8 < 8; ++n8) {
        size_t col = h * 64 + n8 * 8 + cc;
        float2 v0 = {o[n8][0] * inv0, o[n8][1] * inv0};
        float2 v1 = {o[n8][2] * inv1, o[n8][3] * inv1};
        *(float2*)(out + row * 512 + col) = v0;
        *(float2*)(out + (row + 8) * 512 + col) = v1;
    }
}

// ------- fused lo attention + bilinear upsample + add -> fp16 Phi ------------
__global__ __launch_bounds__(256) void lo_fused_kernel(const h16* __restrict__ qkv,
                                                       const float* __restrict__ ahi,
                                                       h16* __restrict__ ph) {
    int gw = (blockIdx.x * 256 + threadIdx.x) >> 5;
    int lane = threadIdx.x & 31;
    int h = gw & 7;
    int w = (gw >> 3) & 1023;
    int b = gw >> 13;
    const h16* base = qkv + (size_t)(b * 4096 + w * 4) * 1536 + h * 64 + lane;
    float q[4][2], k[4][2], v[4][2];
#pragma unroll
    for (int t = 0; t < 4; ++t) {
        const h16* r = base + t * 1536;
        q[t][0] = __half2float(r[0]);    q[t][1] = __half2float(r[32]);
        k[t][0] = __half2float(r[512]);  k[t][1] = __half2float(r[544]);
        v[t][0] = __half2float(r[1024]); v[t][1] = __half2float(r[1056]);
    }
    float lg[4][4];
#pragma unroll
    for (int t = 0; t < 4; ++t)
#pragma unroll
        for (int s2 = 0; s2 < 4; ++s2)
            lg[t][s2] = q[t][0] * k[s2][0] + q[t][1] * k[s2][1];
#pragma unroll
    for (int off = 16; off; off >>= 1)
#pragma unroll
        for (int t = 0; t < 4; ++t)
#pragma unroll
            for (int s2 = 0; s2 < 4; ++s2)
                lg[t][s2] += __shfl_xor_sync(0xffffffffu, lg[t][s2], off);

    int hh = w >> 5, wh = w & 31;
    int c = h * 64 + lane;
    const float* hp = ahi + (size_t)b * 1024 * 512;
#pragma unroll
    for (int t = 0; t < 4; ++t) {
        float L0 = lg[t][0] * 0.125f, L1 = lg[t][1] * 0.125f;
        float L2 = lg[t][2] * 0.125f, L3 = lg[t][3] * 0.125f;
        float m = fmaxf(fmaxf(L0, L1), fmaxf(L2, L3));
        float p0 = __expf(L0 - m), p1 = __expf(L1 - m);
        float p2 = __expf(L2 - m), p3 = __expf(L3 - m);
        float inv = 1.0f / (p0 + p1 + p2 + p3);
        float o0 = (p0 * v[0][0] + p1 * v[1][0] + p2 * v[2][0] + p3 * v[3][0]) * inv;
        float o1 = (p0 * v[0][1] + p1 * v[1][1] + p2 * v[2][1] + p3 * v[3][1]) * inv;

        int y = hh * 2 + (t >> 1), x = wh * 2 + (t & 1);
        float fy = 0.5f * y - 0.25f;
        float fx = 0.5f * x - 0.25f;
        int y0 = (int)floorf(fy), x0 = (int)floorf(fx);
        float wy = fy - (float)y0, wx = fx - (float)x0;
        int y0c = max(y0, 0), y1c = min(y0 + 1, 31);
        int x0c = max(x0, 0), x1c = min(x0 + 1, 31);
        float w00 = (1.f - wy) * (1.f - wx), w01 = (1.f - wy) * wx;
        float w10 = wy * (1.f - wx), w11 = wy * wx;
        size_t p00 = (size_t)(y0c * 32 + x0c) * 512;
        size_t p01 = (size_t)(y0c * 32 + x1c) * 512;
        size_t p10 = (size_t)(y1c * 32 + x0c) * 512;
        size_t p11 = (size_t)(y1c * 32 + x1c) * 512;
        float u0 = w00 * hp[p00 + c] + w01 * hp[p01 + c] +
                   w10 * hp[p10 + c] + w11 * hp[p11 + c];
        float u1 = w00 * hp[p00 + c + 32] + w01 * hp[p01 + c + 32] +
                   w10 * hp[p10 + c + 32] + w11 * hp[p11 + c + 32];

        int tok = y * 64 + x;
        h16* op = ph + (size_t)(b * 4096 + tok) * 512 + c;
        op[0] = __float2half_rn(o0 + u0);
        op[32] = __float2half_rn(o1 + u1);
    }
}

// --------------------------------- launch -----------------------------------
extern "C" void kernel_launch(void* const* d_in, const int* in_sizes, int n_in,
                              void* d_out, int out_size) {
    const float* x     = (const float*)d_in[0];
    const float* Wqkv  = (const float*)d_in[1];
    const float* Wproj = (const float*)d_in[2];
    const float* bproj = (const float*)d_in[3];
    float* out = (float*)d_out;

    h16 *Ahi, *Wqh, *Wph, *Phi, *Qh, *Kh, *Vh, *qcat;
    float *ahi;
    cudaGetSymbolAddress((void**)&Ahi, g_Ahi);
    cudaGetSymbolAddress((void**)&Wqh, g_Wqh);
    cudaGetSymbolAddress((void**)&Wph, g_Wph);
    cudaGetSymbolAddress((void**)&Phi, g_Phi);
    cudaGetSymbolAddress((void**)&qcat, g_qcat);
    cudaGetSymbolAddress((void**)&ahi, g_ahi);
    cudaGetSymbolAddress((void**)&Qh, g_Qh);
    cudaGetSymbolAddress((void**)&Kh, g_Kh);
    cudaGetSymbolAddress((void**)&Vh, g_Vh);

    cudaFuncSetAttribute((const void*)gemm_mma,
                         cudaFuncAttributeMaxDynamicSharedMemorySize, GEMM_SMEM);
    cudaFuncSetAttribute((const void*)hi_attn_mma,
                         cudaFuncAttributeMaxDynamicSharedMemorySize, ATT_SMEM);

    prep_kernel<<<8192, 128>>>(x, Ahi);
    round_kernel<<<768, 256>>>(Wqkv, Wqh, 1536 * 512 / 4);
    round_kernel<<<256, 256>>>(Wproj, Wph, 512 * 512 / 4);

    gemm_mma<<<dim3(12, 320), 256, GEMM_SMEM>>>(Ahi, Wqh, nullptr, nullptr,
                                                qcat, 1536, 1, Qh, Kh, Vh);

    hi_attn_mma<<<dim3(16, 8, 8), 128, ATT_SMEM>>>(Qh, Kh, Vh, ahi);
    lo_fused_kernel<<<8192, 256>>>(qcat + (size_t)8192 * 1536, ahi, Phi);

    gemm_mma<<<dim3(4, 256), 256, GEMM_SMEM>>>(Phi, Wph, bproj, out, nullptr,
                                               512, 0, nullptr, nullptr, nullptr);
}